// round 1
// baseline (speedup 1.0000x reference)
#include <cuda_runtime.h>

#define N_NODES 100000
#define N_EDGES 800000
#define C 64

// Scratch (device globals — no allocation allowed)
__device__ float g_A[N_NODES * C];    // x @ W1_top            (scaled by edge_attr per-edge)
__device__ float g_B[N_NODES * C];    // x @ W1_bot + b1
__device__ float g_H[N_NODES * C];    // scatter accumulator of relu(h)
__device__ float g_deg[N_NODES];      // in-degree (for deg * b2 term)

// ---------------------------------------------------------------------------
// Phase 1: AB[n, 0:64] = x[n] @ W1[0:64, :]         -> g_A
//          AB[n, 64:128] = x[n] @ W1[64:128, :] + b1 -> g_B
// 64-node tile per block, 256 threads (16x16), 4x8 register tile.
// ---------------------------------------------------------------------------
__global__ __launch_bounds__(256) void phase1_kernel(
    const float* __restrict__ x,
    const float* __restrict__ W1,
    const float* __restrict__ b1)
{
    __shared__ float xs[64][64];    // [local node][k]
    __shared__ float ws[64][128];   // [k][j]  j<64 -> A weights, j>=64 -> B weights

    const int t = threadIdx.x;
    const int node0 = blockIdx.x * 64;

    // Load x tile (coalesced float4 per node row); zero-fill OOB nodes.
    for (int i = t; i < 64 * 16; i += 256) {
        int n  = i >> 4;
        int kc = (i & 15) * 4;
        float4 v = make_float4(0.f, 0.f, 0.f, 0.f);
        int gn = node0 + n;
        if (gn < N_NODES) v = *(const float4*)(x + gn * C + kc);
        xs[n][kc + 0] = v.x; xs[n][kc + 1] = v.y;
        xs[n][kc + 2] = v.z; xs[n][kc + 3] = v.w;
    }
    // Load W1 into ws[k][j]: A-half and B-half side by side.
    for (int i = t; i < 64 * 128; i += 256) {
        int k = i >> 7;
        int j = i & 127;
        ws[k][j] = (j < 64) ? W1[k * 64 + j] : W1[(64 + k) * 64 + (j - 64)];
    }
    __syncthreads();

    const int tx = t & 15;
    const int ty = t >> 4;

    float acc[4][8];
    #pragma unroll
    for (int a = 0; a < 4; a++)
        #pragma unroll
        for (int b = 0; b < 8; b++) acc[a][b] = 0.f;

    #pragma unroll 4
    for (int k = 0; k < 64; k++) {
        float xv[4], wv[8];
        #pragma unroll
        for (int a = 0; a < 4; a++) xv[a] = xs[ty + 16 * a][k];
        #pragma unroll
        for (int b = 0; b < 8; b++) wv[b] = ws[k][tx + 16 * b];
        #pragma unroll
        for (int a = 0; a < 4; a++)
            #pragma unroll
            for (int b = 0; b < 8; b++) acc[a][b] = fmaf(xv[a], wv[b], acc[a][b]);
    }

    #pragma unroll
    for (int a = 0; a < 4; a++) {
        int gn = node0 + ty + 16 * a;
        if (gn >= N_NODES) continue;
        #pragma unroll
        for (int b = 0; b < 8; b++) {
            int j = tx + 16 * b;
            if (j < 64) g_A[gn * C + j] = acc[a][b];
            else        g_B[gn * C + (j - 64)] = acc[a][b] + b1[j - 64];
        }
    }
}

// ---------------------------------------------------------------------------
// Phase 2 (edge): H[col] += relu(ea * A[row] + B[col]); deg[col] += 1
// 16 lanes per edge, float4 per lane. Handles int32 OR int64 edge_index.
// ---------------------------------------------------------------------------
__global__ __launch_bounds__(256) void edge_kernel(
    const void* __restrict__ ei_raw,
    const float* __restrict__ ea)
{
    const int tid = blockIdx.x * 256 + threadIdx.x;
    const int e = tid >> 4;
    if (e >= N_EDGES) return;
    const int lane = tid & 15;

    // Detect index dtype: int64 values < 2^31 have zero high words (little-endian
    // odd int32 slots). For int32 data those slots are random node ids -> ~never all 0.
    const int* e32 = (const int*)ei_raw;
    bool is64 = ((e32[1] | e32[3] | e32[5] | e32[7] |
                  e32[9] | e32[11] | e32[13] | e32[15]) == 0);

    int row, col;
    if (is64) {
        const long long* e64 = (const long long*)ei_raw;
        row = (int)e64[e];
        col = (int)e64[N_EDGES + e];
    } else {
        row = e32[e];
        col = e32[N_EDGES + e];
    }
    const float w = ea[e];

    float4 a = *(const float4*)(g_A + row * C + lane * 4);
    float4 b = *(const float4*)(g_B + col * C + lane * 4);

    float4 v;
    v.x = fmaxf(fmaf(w, a.x, b.x), 0.f);
    v.y = fmaxf(fmaf(w, a.y, b.y), 0.f);
    v.z = fmaxf(fmaf(w, a.z, b.z), 0.f);
    v.w = fmaxf(fmaf(w, a.w, b.w), 0.f);

    atomicAdd((float4*)(g_H + col * C + lane * 4), v);
    if (lane == 0) atomicAdd(&g_deg[col], 1.0f);
}

// ---------------------------------------------------------------------------
// Phase 3: out[n] = H[n] @ W2 + deg[n] * b2
// 64-node tile, 256 threads (16x16), 4x4 register tile.
// ---------------------------------------------------------------------------
__global__ __launch_bounds__(256) void phase3_kernel(
    float* __restrict__ out,
    const float* __restrict__ W2,
    const float* __restrict__ b2)
{
    __shared__ float hs[64][64];   // [local node][k]
    __shared__ float ws[64][64];   // [k][j]

    const int t = threadIdx.x;
    const int node0 = blockIdx.x * 64;

    for (int i = t; i < 64 * 16; i += 256) {
        int n  = i >> 4;
        int kc = (i & 15) * 4;
        float4 v = make_float4(0.f, 0.f, 0.f, 0.f);
        int gn = node0 + n;
        if (gn < N_NODES) v = *(const float4*)(g_H + gn * C + kc);
        hs[n][kc + 0] = v.x; hs[n][kc + 1] = v.y;
        hs[n][kc + 2] = v.z; hs[n][kc + 3] = v.w;
    }
    for (int i = t; i < 64 * 64; i += 256) {
        ws[i >> 6][i & 63] = W2[i];
    }
    __syncthreads();

    const int tx = t & 15;
    const int ty = t >> 4;

    float acc[4][4];
    #pragma unroll
    for (int a = 0; a < 4; a++)
        #pragma unroll
        for (int b = 0; b < 4; b++) acc[a][b] = 0.f;

    #pragma unroll 4
    for (int k = 0; k < 64; k++) {
        float hv[4], wv[4];
        #pragma unroll
        for (int a = 0; a < 4; a++) hv[a] = hs[ty + 16 * a][k];
        #pragma unroll
        for (int b = 0; b < 4; b++) wv[b] = ws[k][tx + 16 * b];
        #pragma unroll
        for (int a = 0; a < 4; a++)
            #pragma unroll
            for (int b = 0; b < 4; b++) acc[a][b] = fmaf(hv[a], wv[b], acc[a][b]);
    }

    #pragma unroll
    for (int a = 0; a < 4; a++) {
        int gn = node0 + ty + 16 * a;
        if (gn >= N_NODES) continue;
        float d = g_deg[gn];
        #pragma unroll
        for (int b = 0; b < 4; b++) {
            int j = tx + 16 * b;
            out[gn * C + j] = acc[a][b] + d * b2[j];
        }
    }
}

// ---------------------------------------------------------------------------
extern "C" void kernel_launch(void* const* d_in, const int* in_sizes, int n_in,
                              void* d_out, int out_size)
{
    const float* x  = (const float*)d_in[0];
    const void*  ei = (const void*)d_in[1];   // int32 or int64, detected on device
    const float* ea = (const float*)d_in[2];
    const float* W1 = (const float*)d_in[3];
    const float* b1 = (const float*)d_in[4];
    const float* W2 = (const float*)d_in[5];
    const float* b2 = (const float*)d_in[6];
    float* out = (float*)d_out;

    void* hptr; void* dptr;
    cudaGetSymbolAddress(&hptr, g_H);
    cudaGetSymbolAddress(&dptr, g_deg);
    cudaMemsetAsync(hptr, 0, (size_t)N_NODES * C * sizeof(float));
    cudaMemsetAsync(dptr, 0, (size_t)N_NODES * sizeof(float));

    const int node_blocks = (N_NODES + 63) / 64;
    phase1_kernel<<<node_blocks, 256>>>(x, W1, b1);

    const long long edge_threads = (long long)N_EDGES * 16;
    const int edge_blocks = (int)((edge_threads + 255) / 256);
    edge_kernel<<<edge_blocks, 256>>>(ei, ea);

    phase3_kernel<<<node_blocks, 256>>>(out, W2, b2);
}

// round 2
// speedup vs baseline: 1.0787x; 1.0787x over previous
#include <cuda_runtime.h>

#define N_NODES 100000
#define N_EDGES 800000
#define C 64

// Scratch (device globals — no allocation allowed)
__device__ float g_A[N_NODES * C];    // x @ W1_top  (scaled by edge_attr per-edge)
__device__ float g_B[N_NODES * C];    // x @ W1_bot + b1
__device__ float g_H[N_NODES * C];    // scatter accumulator of relu(h)
__device__ float g_deg[N_NODES];      // in-degree (for deg * b2 term)
__device__ int   g_is64;              // edge_index dtype flag (written by phase1)

// ---------------------------------------------------------------------------
// Phase 1: g_A[n,:] = x[n] @ W1[0:64,:]
//          g_B[n,:] = x[n] @ W1[64:128,:] + b1
// Also zeroes g_H / g_deg for its node slice and writes the dtype flag.
// 64-node tile, 256 threads (tx 0..15 -> 4 output cols each half, ty 0..15 ->
// 4 nodes each). Per k: 4 scalar LDS (broadcast) + 2 LDS.128 (conflict-free),
// 32 FMA.
// ---------------------------------------------------------------------------
__global__ __launch_bounds__(256) void phase1_kernel(
    const float* __restrict__ x,
    const float* __restrict__ W1,
    const float* __restrict__ b1,
    const int*   __restrict__ ei_probe)
{
    __shared__ float xs[64][64];    // [local node][k]
    __shared__ float ws[64][128];   // [k][j]  j<64 -> A weights, j>=64 -> B weights

    const int t = threadIdx.x;
    const int node0 = blockIdx.x * 64;

    // dtype probe: int64 indices < 2^31 have zero high words.
    if (blockIdx.x == 0 && t == 0) {
        g_is64 = ((ei_probe[1] | ei_probe[3] | ei_probe[5] | ei_probe[7] |
                   ei_probe[9] | ei_probe[11] | ei_probe[13] | ei_probe[15]) == 0);
    }

    // Zero this block's slice of g_H (4096 floats) and g_deg.
    {
        const float4 z = make_float4(0.f, 0.f, 0.f, 0.f);
        long long base = (long long)node0 * C;
        for (int i = t; i < 64 * 16; i += 256) {
            long long off = base + (long long)i * 4;
            if (off < (long long)N_NODES * C) *(float4*)(g_H + off) = z;
        }
        if (t < 64 && node0 + t < N_NODES) g_deg[node0 + t] = 0.f;
    }

    // Load x tile (coalesced float4 per node row); zero-fill OOB nodes.
    for (int i = t; i < 64 * 16; i += 256) {
        int n  = i >> 4;
        int kc = (i & 15) * 4;
        float4 v = make_float4(0.f, 0.f, 0.f, 0.f);
        int gn = node0 + n;
        if (gn < N_NODES) v = *(const float4*)(x + (long long)gn * C + kc);
        xs[n][kc + 0] = v.x; xs[n][kc + 1] = v.y;
        xs[n][kc + 2] = v.z; xs[n][kc + 3] = v.w;
    }
    // W1 tile: A-half and B-half side by side.
    for (int i = t; i < 64 * 128; i += 256) {
        int k = i >> 7;
        int j = i & 127;
        ws[k][j] = (j < 64) ? W1[k * 64 + j] : W1[(64 + k) * 64 + (j - 64)];
    }
    __syncthreads();

    const int tx = t & 15;    // output col group: A cols tx*4.., B cols 64+tx*4..
    const int ty = t >> 4;    // node group: nodes ty*4..ty*4+3

    float acc[4][8];
    #pragma unroll
    for (int a = 0; a < 4; a++)
        #pragma unroll
        for (int b = 0; b < 8; b++) acc[a][b] = 0.f;

    #pragma unroll 4
    for (int k = 0; k < 64; k++) {
        float4 wA = *(const float4*)&ws[k][tx * 4];
        float4 wB = *(const float4*)&ws[k][64 + tx * 4];
        float xv[4];
        #pragma unroll
        for (int a = 0; a < 4; a++) xv[a] = xs[ty * 4 + a][k];
        #pragma unroll
        for (int a = 0; a < 4; a++) {
            acc[a][0] = fmaf(xv[a], wA.x, acc[a][0]);
            acc[a][1] = fmaf(xv[a], wA.y, acc[a][1]);
            acc[a][2] = fmaf(xv[a], wA.z, acc[a][2]);
            acc[a][3] = fmaf(xv[a], wA.w, acc[a][3]);
            acc[a][4] = fmaf(xv[a], wB.x, acc[a][4]);
            acc[a][5] = fmaf(xv[a], wB.y, acc[a][5]);
            acc[a][6] = fmaf(xv[a], wB.z, acc[a][6]);
            acc[a][7] = fmaf(xv[a], wB.w, acc[a][7]);
        }
    }

    float4 bv = *(const float4*)(b1 + tx * 4);
    #pragma unroll
    for (int a = 0; a < 4; a++) {
        int gn = node0 + ty * 4 + a;
        if (gn >= N_NODES) continue;
        float4 va = make_float4(acc[a][0], acc[a][1], acc[a][2], acc[a][3]);
        float4 vb = make_float4(acc[a][4] + bv.x, acc[a][5] + bv.y,
                                acc[a][6] + bv.z, acc[a][7] + bv.w);
        *(float4*)(g_A + (long long)gn * C + tx * 4) = va;
        *(float4*)(g_B + (long long)gn * C + tx * 4) = vb;
    }
}

// ---------------------------------------------------------------------------
// Phase 2 (edge): H[col] += relu(ea * A[row] + B[col]); deg[col] += 1
// 16 lanes per edge, float4 per lane.
// ---------------------------------------------------------------------------
__global__ __launch_bounds__(256) void edge_kernel(
    const void* __restrict__ ei_raw,
    const float* __restrict__ ea)
{
    const int tid = blockIdx.x * 256 + threadIdx.x;
    const int e = tid >> 4;
    if (e >= N_EDGES) return;
    const int lane = tid & 15;

    int row, col;
    if (g_is64) {
        const long long* e64 = (const long long*)ei_raw;
        row = (int)e64[e];
        col = (int)e64[N_EDGES + e];
    } else {
        const int* e32 = (const int*)ei_raw;
        row = e32[e];
        col = e32[N_EDGES + e];
    }
    const float w = ea[e];

    float4 a = *(const float4*)(g_A + (long long)row * C + lane * 4);
    float4 b = *(const float4*)(g_B + (long long)col * C + lane * 4);

    float4 v;
    v.x = fmaxf(fmaf(w, a.x, b.x), 0.f);
    v.y = fmaxf(fmaf(w, a.y, b.y), 0.f);
    v.z = fmaxf(fmaf(w, a.z, b.z), 0.f);
    v.w = fmaxf(fmaf(w, a.w, b.w), 0.f);

    atomicAdd((float4*)(g_H + (long long)col * C + lane * 4), v);
    if (lane == 0) atomicAdd(&g_deg[col], 1.0f);
}

// ---------------------------------------------------------------------------
// Phase 3: out[n] = H[n] @ W2 + deg[n] * b2
// 64-node tile, 256 threads, 4 nodes x 4 cols per thread.
// Per k: 4 scalar LDS + 1 LDS.128, 16 FMA.
// ---------------------------------------------------------------------------
__global__ __launch_bounds__(256) void phase3_kernel(
    float* __restrict__ out,
    const float* __restrict__ W2,
    const float* __restrict__ b2)
{
    __shared__ float hs[64][64];   // [local node][k]
    __shared__ float ws[64][64];   // [k][j]

    const int t = threadIdx.x;
    const int node0 = blockIdx.x * 64;

    for (int i = t; i < 64 * 16; i += 256) {
        int n  = i >> 4;
        int kc = (i & 15) * 4;
        float4 v = make_float4(0.f, 0.f, 0.f, 0.f);
        int gn = node0 + n;
        if (gn < N_NODES) v = *(const float4*)(g_H + (long long)gn * C + kc);
        hs[n][kc + 0] = v.x; hs[n][kc + 1] = v.y;
        hs[n][kc + 2] = v.z; hs[n][kc + 3] = v.w;
    }
    for (int i = t; i < 64 * 64; i += 256) {
        ws[i >> 6][i & 63] = W2[i];
    }
    __syncthreads();

    const int tx = t & 15;
    const int ty = t >> 4;

    float acc[4][4];
    #pragma unroll
    for (int a = 0; a < 4; a++)
        #pragma unroll
        for (int b = 0; b < 4; b++) acc[a][b] = 0.f;

    #pragma unroll 4
    for (int k = 0; k < 64; k++) {
        float4 wv = *(const float4*)&ws[k][tx * 4];
        float hv[4];
        #pragma unroll
        for (int a = 0; a < 4; a++) hv[a] = hs[ty * 4 + a][k];
        #pragma unroll
        for (int a = 0; a < 4; a++) {
            acc[a][0] = fmaf(hv[a], wv.x, acc[a][0]);
            acc[a][1] = fmaf(hv[a], wv.y, acc[a][1]);
            acc[a][2] = fmaf(hv[a], wv.z, acc[a][2]);
            acc[a][3] = fmaf(hv[a], wv.w, acc[a][3]);
        }
    }

    float4 b2v = *(const float4*)(b2 + tx * 4);
    #pragma unroll
    for (int a = 0; a < 4; a++) {
        int gn = node0 + ty * 4 + a;
        if (gn >= N_NODES) continue;
        float d = g_deg[gn];
        float4 v = make_float4(acc[a][0] + d * b2v.x, acc[a][1] + d * b2v.y,
                               acc[a][2] + d * b2v.z, acc[a][3] + d * b2v.w);
        *(float4*)(out + (long long)gn * C + tx * 4) = v;
    }
}

// ---------------------------------------------------------------------------
extern "C" void kernel_launch(void* const* d_in, const int* in_sizes, int n_in,
                              void* d_out, int out_size)
{
    const float* x  = (const float*)d_in[0];
    const void*  ei = (const void*)d_in[1];   // int32 or int64, detected on device
    const float* ea = (const float*)d_in[2];
    const float* W1 = (const float*)d_in[3];
    const float* b1 = (const float*)d_in[4];
    const float* W2 = (const float*)d_in[5];
    const float* b2 = (const float*)d_in[6];
    float* out = (float*)d_out;

    const int node_blocks = (N_NODES + 63) / 64;
    phase1_kernel<<<node_blocks, 256>>>(x, W1, b1, (const int*)ei);

    const int edge_blocks = (N_EDGES * 16) / 256;   // 50000, exact
    edge_kernel<<<edge_blocks, 256>>>(ei, ea);

    phase3_kernel<<<node_blocks, 256>>>(out, W2, b2);
}

// round 4
// speedup vs baseline: 1.2400x; 1.1495x over previous
#include <cuda_runtime.h>
#include <cuda_fp16.h>

#define N_NODES 100000
#define N_EDGES 800000
#define C 64

// Scratch (device globals — no allocation allowed)
__device__ __half g_A[N_NODES * C];   // fp16: x @ W1_top
__device__ __half g_B[N_NODES * C];   // fp16: x @ W1_bot + b1
__device__ float  g_H[N_NODES * C];   // fp32 scatter accumulator of relu(h)
__device__ float  g_deg[N_NODES];     // in-degree (for deg * b2 term)
__device__ int    g_is64;             // edge_index dtype flag

// ---------------------------------------------------------------------------
// Phase 1: g_A[n,:] = half(x[n] @ W1[0:64,:])
//          g_B[n,:] = half(x[n] @ W1[64:128,:] + b1)
// Also zeroes g_H / g_deg slice and writes dtype flag.
// 64-node tile, 256 threads. Main loop k-chunked by 4:
// per chunk 12 LDS.128 for 128 FMA.
// ---------------------------------------------------------------------------
__global__ __launch_bounds__(256) void phase1_kernel(
    const float* __restrict__ x,
    const float* __restrict__ W1,
    const float* __restrict__ b1,
    const int*   __restrict__ ei_probe)
{
    __shared__ float xs[64][64];    // [local node][k]
    __shared__ float ws[64][128];   // [k][j]  j<64 -> A weights, j>=64 -> B weights

    const int t = threadIdx.x;
    const int node0 = blockIdx.x * 64;

    if (blockIdx.x == 0 && t == 0) {
        g_is64 = ((ei_probe[1] | ei_probe[3] | ei_probe[5] | ei_probe[7] |
                   ei_probe[9] | ei_probe[11] | ei_probe[13] | ei_probe[15]) == 0);
    }

    // Zero this block's slice of g_H and g_deg.
    {
        const float4 z = make_float4(0.f, 0.f, 0.f, 0.f);
        long long base = (long long)node0 * C;
        for (int i = t; i < 64 * 16; i += 256) {
            long long off = base + (long long)i * 4;
            if (off < (long long)N_NODES * C) *(float4*)(g_H + off) = z;
        }
        if (t < 64 && node0 + t < N_NODES) g_deg[node0 + t] = 0.f;
    }

    // Load x tile (coalesced float4 per node row); zero-fill OOB.
    for (int i = t; i < 64 * 16; i += 256) {
        int n  = i >> 4;
        int kc = (i & 15) * 4;
        float4 v = make_float4(0.f, 0.f, 0.f, 0.f);
        int gn = node0 + n;
        if (gn < N_NODES) v = *(const float4*)(x + (long long)gn * C + kc);
        *(float4*)&xs[n][kc] = v;
    }
    // W1 tile: A-half and B-half side by side.
    for (int i = t; i < 64 * 128; i += 256) {
        int k = i >> 7;
        int j = i & 127;
        ws[k][j] = (j < 64) ? W1[k * 64 + j] : W1[(64 + k) * 64 + (j - 64)];
    }
    __syncthreads();

    const int tx = t & 15;    // output col group (4 cols each half)
    const int ty = t >> 4;    // node group (4 nodes)

    float acc[4][8];
    #pragma unroll
    for (int a = 0; a < 4; a++)
        #pragma unroll
        for (int b = 0; b < 8; b++) acc[a][b] = 0.f;

    #pragma unroll 2
    for (int k0 = 0; k0 < 64; k0 += 4) {
        float4 xv[4];
        #pragma unroll
        for (int a = 0; a < 4; a++) xv[a] = *(const float4*)&xs[ty * 4 + a][k0];

        #pragma unroll
        for (int j = 0; j < 4; j++) {
            float4 wA = *(const float4*)&ws[k0 + j][tx * 4];
            float4 wB = *(const float4*)&ws[k0 + j][64 + tx * 4];
            #pragma unroll
            for (int a = 0; a < 4; a++) {
                float xk = (j == 0) ? xv[a].x : (j == 1) ? xv[a].y :
                           (j == 2) ? xv[a].z : xv[a].w;
                acc[a][0] = fmaf(xk, wA.x, acc[a][0]);
                acc[a][1] = fmaf(xk, wA.y, acc[a][1]);
                acc[a][2] = fmaf(xk, wA.z, acc[a][2]);
                acc[a][3] = fmaf(xk, wA.w, acc[a][3]);
                acc[a][4] = fmaf(xk, wB.x, acc[a][4]);
                acc[a][5] = fmaf(xk, wB.y, acc[a][5]);
                acc[a][6] = fmaf(xk, wB.z, acc[a][6]);
                acc[a][7] = fmaf(xk, wB.w, acc[a][7]);
            }
        }
    }

    float4 bv = *(const float4*)(b1 + tx * 4);
    #pragma unroll
    for (int a = 0; a < 4; a++) {
        int gn = node0 + ty * 4 + a;
        if (gn >= N_NODES) continue;
        __half2 a01 = __floats2half2_rn(acc[a][0], acc[a][1]);
        __half2 a23 = __floats2half2_rn(acc[a][2], acc[a][3]);
        __half2 b01 = __floats2half2_rn(acc[a][4] + bv.x, acc[a][5] + bv.y);
        __half2 b23 = __floats2half2_rn(acc[a][6] + bv.z, acc[a][7] + bv.w);
        // store as two half2 (8B total per array), 8B-aligned
        *(__half2*)(g_A + (long long)gn * C + tx * 4)     = a01;
        *(__half2*)(g_A + (long long)gn * C + tx * 4 + 2) = a23;
        *(__half2*)(g_B + (long long)gn * C + tx * 4)     = b01;
        *(__half2*)(g_B + (long long)gn * C + tx * 4 + 2) = b23;
    }
}

// ---------------------------------------------------------------------------
// Phase 2 (edge): H[col] += relu(ea * A[row] + B[col]); deg[col] += 1
// 16 lanes per edge; each lane handles 4 channels (8B fp16 loads, fp32 math,
// float4 atomic).
// ---------------------------------------------------------------------------
__global__ __launch_bounds__(256) void edge_kernel(
    const void* __restrict__ ei_raw,
    const float* __restrict__ ea)
{
    const int tid = blockIdx.x * 256 + threadIdx.x;
    const int e = tid >> 4;
    if (e >= N_EDGES) return;
    const int lane = tid & 15;

    int row, col;
    if (g_is64) {
        const long long* e64 = (const long long*)ei_raw;
        row = (int)e64[e];
        col = (int)e64[N_EDGES + e];
    } else {
        const int* e32 = (const int*)ei_raw;
        row = e32[e];
        col = e32[N_EDGES + e];
    }
    const float w = ea[e];

    const __half2* ap = (const __half2*)(g_A + (long long)row * C + lane * 4);
    const __half2* bp = (const __half2*)(g_B + (long long)col * C + lane * 4);
    __half2 a01 = ap[0], a23 = ap[1];
    __half2 b01 = bp[0], b23 = bp[1];

    float2 fa01 = __half22float2(a01), fa23 = __half22float2(a23);
    float2 fb01 = __half22float2(b01), fb23 = __half22float2(b23);

    float4 v;
    v.x = fmaxf(fmaf(w, fa01.x, fb01.x), 0.f);
    v.y = fmaxf(fmaf(w, fa01.y, fb01.y), 0.f);
    v.z = fmaxf(fmaf(w, fa23.x, fb23.x), 0.f);
    v.w = fmaxf(fmaf(w, fa23.y, fb23.y), 0.f);

    atomicAdd((float4*)(g_H + (long long)col * C + lane * 4), v);
    if (lane == 0) atomicAdd(&g_deg[col], 1.0f);
}

// ---------------------------------------------------------------------------
// Phase 3: out[n] = H[n] @ W2 + deg[n] * b2   (k-chunked by 4)
// ---------------------------------------------------------------------------
__global__ __launch_bounds__(256) void phase3_kernel(
    float* __restrict__ out,
    const float* __restrict__ W2,
    const float* __restrict__ b2)
{
    __shared__ float hs[64][64];   // [local node][k]
    __shared__ float ws[64][64];   // [k][j]

    const int t = threadIdx.x;
    const int node0 = blockIdx.x * 64;

    for (int i = t; i < 64 * 16; i += 256) {
        int n  = i >> 4;
        int kc = (i & 15) * 4;
        float4 v = make_float4(0.f, 0.f, 0.f, 0.f);
        int gn = node0 + n;
        if (gn < N_NODES) v = *(const float4*)(g_H + (long long)gn * C + kc);
        *(float4*)&hs[n][kc] = v;
    }
    for (int i = t; i < 64 * 64; i += 256) {
        ws[i >> 6][i & 63] = W2[i];
    }
    __syncthreads();

    const int tx = t & 15;
    const int ty = t >> 4;

    float acc[4][4];
    #pragma unroll
    for (int a = 0; a < 4; a++)
        #pragma unroll
        for (int b = 0; b < 4; b++) acc[a][b] = 0.f;

    #pragma unroll 2
    for (int k0 = 0; k0 < 64; k0 += 4) {
        float4 hv[4];
        #pragma unroll
        for (int a = 0; a < 4; a++) hv[a] = *(const float4*)&hs[ty * 4 + a][k0];

        #pragma unroll
        for (int j = 0; j < 4; j++) {
            float4 wv = *(const float4*)&ws[k0 + j][tx * 4];
            #pragma unroll
            for (int a = 0; a < 4; a++) {
                float hk = (j == 0) ? hv[a].x : (j == 1) ? hv[a].y :
                           (j == 2) ? hv[a].z : hv[a].w;
                acc[a][0] = fmaf(hk, wv.x, acc[a][0]);
                acc[a][1] = fmaf(hk, wv.y, acc[a][1]);
                acc[a][2] = fmaf(hk, wv.z, acc[a][2]);
                acc[a][3] = fmaf(hk, wv.w, acc[a][3]);
            }
        }
    }

    float4 b2v = *(const float4*)(b2 + tx * 4);
    #pragma unroll
    for (int a = 0; a < 4; a++) {
        int gn = node0 + ty * 4 + a;
        if (gn >= N_NODES) continue;
        float d = g_deg[gn];
        float4 v = make_float4(acc[a][0] + d * b2v.x, acc[a][1] + d * b2v.y,
                               acc[a][2] + d * b2v.z, acc[a][3] + d * b2v.w);
        *(float4*)(out + (long long)gn * C + tx * 4) = v;
    }
}

// ---------------------------------------------------------------------------
extern "C" void kernel_launch(void* const* d_in, const int* in_sizes, int n_in,
                              void* d_out, int out_size)
{
    const float* x  = (const float*)d_in[0];
    const void*  ei = (const void*)d_in[1];   // int32 or int64, detected on device
    const float* ea = (const float*)d_in[2];
    const float* W1 = (const float*)d_in[3];
    const float* b1 = (const float*)d_in[4];
    const float* W2 = (const float*)d_in[5];
    const float* b2 = (const float*)d_in[6];
    float* out = (float*)d_out;

    const int node_blocks = (N_NODES + 63) / 64;
    phase1_kernel<<<node_blocks, 256>>>(x, W1, b1, (const int*)ei);

    const int edge_blocks = (N_EDGES * 16) / 256;   // 50000, exact
    edge_kernel<<<edge_blocks, 256>>>(ei, ea);

    phase3_kernel<<<node_blocks, 256>>>(out, W2, b2);
}

// round 5
// speedup vs baseline: 1.5001x; 1.2098x over previous
#include <cuda_runtime.h>
#include <cuda_fp16.h>

#define N_NODES 100000
#define N_EDGES 800000
#define C 64

// Scratch (device globals — no allocation allowed)
__device__ __half g_A[N_NODES * C];   // fp16: x @ W1_top
__device__ __half g_B[N_NODES * C];   // fp16: x @ W1_bot + b1
__device__ float  g_H[N_NODES * C];   // fp32 scatter accumulator of relu(h)
__device__ float  g_deg[N_NODES];     // in-degree
__device__ int    g_is64;             // edge_index dtype flag

// ---- tf32 helpers -----------------------------------------------------------
__device__ __forceinline__ float round_tf32(float x) {
    unsigned u;
    asm("cvt.rna.tf32.f32 %0, %1;" : "=r"(u) : "f"(x));
    return __uint_as_float(u);
}

__device__ __forceinline__ void mma_tf32(
    float& c0, float& c1, float& c2, float& c3,
    unsigned a0, unsigned a1, unsigned a2, unsigned a3,
    unsigned b0, unsigned b1)
{
    asm volatile(
        "mma.sync.aligned.m16n8k8.row.col.f32.tf32.tf32.f32 "
        "{%0,%1,%2,%3},{%4,%5,%6,%7},{%8,%9},{%0,%1,%2,%3};"
        : "+f"(c0), "+f"(c1), "+f"(c2), "+f"(c3)
        : "r"(a0), "r"(a1), "r"(a2), "r"(a3), "r"(b0), "r"(b1));
}

// ---------------------------------------------------------------------------
// Phase 1 (tensor): g_A[n,:] = half(x[n] @ W1[0:64,:])
//                   g_B[n,:] = half(x[n] @ W1[64:128,:] + b1)
// 128-node tile, 256 threads = 8 warps, each warp owns an m16 row slab and
// all 16 n8 tiles (N=128 combined A|B). K=64 processed in two 32-wide stages.
// Also zeroes g_H / g_deg slice and writes the dtype flag.
// ---------------------------------------------------------------------------
__global__ __launch_bounds__(256) void phase1_kernel(
    const float* __restrict__ x,
    const float* __restrict__ W1,
    const float* __restrict__ bias1,
    const int*   __restrict__ ei_probe)
{
    __shared__ float xs[128][36];    // [node][k-local], pad 36 -> banks 4g+t4
    __shared__ float ws[32][136];    // [k-local][j 0..127], pad 136 -> banks 8t4+g

    const int t    = threadIdx.x;
    const int warp = t >> 5;
    const int lane = t & 31;
    const int gid  = lane >> 2;     // 0..7
    const int t4   = lane & 3;      // 0..3
    const int node0 = blockIdx.x * 128;

    if (blockIdx.x == 0 && t == 0) {
        g_is64 = ((ei_probe[1] | ei_probe[3] | ei_probe[5] | ei_probe[7] |
                   ei_probe[9] | ei_probe[11] | ei_probe[13] | ei_probe[15]) == 0);
    }

    // Zero this block's slice of g_H (128*64 floats) and g_deg.
    {
        const float4 z = make_float4(0.f, 0.f, 0.f, 0.f);
        long long base = (long long)node0 * C;
        for (int i = t; i < 128 * 16; i += 256) {
            long long off = base + (long long)i * 4;
            if (off < (long long)N_NODES * C) *(float4*)(g_H + off) = z;
        }
        for (int i = t; i < 128; i += 256) {
            int gn = node0 + i;
            if (gn < N_NODES) g_deg[gn] = 0.f;
        }
    }

    float acc[16][4];
    #pragma unroll
    for (int nt = 0; nt < 16; nt++)
        #pragma unroll
        for (int q = 0; q < 4; q++) acc[nt][q] = 0.f;

    #pragma unroll 1
    for (int stage = 0; stage < 2; stage++) {
        const int ks0 = stage * 32;

        // Load X tile [128 nodes][32 k], tf32-rounded.
        for (int i = t; i < 128 * 8; i += 256) {
            int n  = i >> 3;
            int kc = (i & 7) * 4;
            float4 v = make_float4(0.f, 0.f, 0.f, 0.f);
            int gn = node0 + n;
            if (gn < N_NODES) v = *(const float4*)(x + (long long)gn * C + ks0 + kc);
            xs[n][kc + 0] = round_tf32(v.x);
            xs[n][kc + 1] = round_tf32(v.y);
            xs[n][kc + 2] = round_tf32(v.z);
            xs[n][kc + 3] = round_tf32(v.w);
        }
        // Load W tile [32 k][128 j]: j<64 -> W1[ks0+k][j], j>=64 -> W1[64+ks0+k][j-64].
        for (int i = t; i < 32 * 32; i += 256) {
            int k  = i >> 5;
            int jc = (i & 31) * 4;
            const float* src = (jc < 64)
                ? (W1 + (ks0 + k) * 64 + jc)
                : (W1 + (64 + ks0 + k) * 64 + (jc - 64));
            float4 v = *(const float4*)src;
            ws[k][jc + 0] = round_tf32(v.x);
            ws[k][jc + 1] = round_tf32(v.y);
            ws[k][jc + 2] = round_tf32(v.z);
            ws[k][jc + 3] = round_tf32(v.w);
        }
        __syncthreads();

        const int m0 = warp * 16;
        #pragma unroll
        for (int slab = 0; slab < 4; slab++) {
            const int ks = slab * 8;
            unsigned a0 = __float_as_uint(xs[m0 + gid    ][ks + t4    ]);
            unsigned a1 = __float_as_uint(xs[m0 + gid + 8][ks + t4    ]);
            unsigned a2 = __float_as_uint(xs[m0 + gid    ][ks + t4 + 4]);
            unsigned a3 = __float_as_uint(xs[m0 + gid + 8][ks + t4 + 4]);
            #pragma unroll
            for (int nt = 0; nt < 16; nt++) {
                unsigned b0 = __float_as_uint(ws[ks + t4    ][nt * 8 + gid]);
                unsigned b1 = __float_as_uint(ws[ks + t4 + 4][nt * 8 + gid]);
                mma_tf32(acc[nt][0], acc[nt][1], acc[nt][2], acc[nt][3],
                         a0, a1, a2, a3, b0, b1);
            }
        }
        __syncthreads();
    }

    // Epilogue: c0,c1 -> (row gid, cols col,col+1); c2,c3 -> (row gid+8, same cols)
    const int r0 = node0 + warp * 16 + gid;
    const int r1 = r0 + 8;
    #pragma unroll
    for (int nt = 0; nt < 16; nt++) {
        int col = nt * 8 + 2 * t4;
        if (col < 64) {
            if (r0 < N_NODES)
                *(__half2*)(g_A + (long long)r0 * C + col) = __floats2half2_rn(acc[nt][0], acc[nt][1]);
            if (r1 < N_NODES)
                *(__half2*)(g_A + (long long)r1 * C + col) = __floats2half2_rn(acc[nt][2], acc[nt][3]);
        } else {
            int c = col - 64;
            float bx = bias1[c], by = bias1[c + 1];
            if (r0 < N_NODES)
                *(__half2*)(g_B + (long long)r0 * C + c) = __floats2half2_rn(acc[nt][0] + bx, acc[nt][1] + by);
            if (r1 < N_NODES)
                *(__half2*)(g_B + (long long)r1 * C + c) = __floats2half2_rn(acc[nt][2] + bx, acc[nt][3] + by);
        }
    }
}

// ---------------------------------------------------------------------------
// Phase 2 (edge): H[col] += relu(ea * A[row] + B[col]); deg[col] += 1
// 16 lanes per edge; fp16 gathers, fp32 math, float4 atomics.
// ---------------------------------------------------------------------------
__global__ __launch_bounds__(256) void edge_kernel(
    const void* __restrict__ ei_raw,
    const float* __restrict__ ea)
{
    const int tid = blockIdx.x * 256 + threadIdx.x;
    const int e = tid >> 4;
    if (e >= N_EDGES) return;
    const int lane = tid & 15;

    int row, col;
    if (g_is64) {
        const long long* e64 = (const long long*)ei_raw;
        row = (int)e64[e];
        col = (int)e64[N_EDGES + e];
    } else {
        const int* e32 = (const int*)ei_raw;
        row = e32[e];
        col = e32[N_EDGES + e];
    }
    const float w = ea[e];

    const __half2* ap = (const __half2*)(g_A + (long long)row * C + lane * 4);
    const __half2* bp = (const __half2*)(g_B + (long long)col * C + lane * 4);
    __half2 a01 = ap[0], a23 = ap[1];
    __half2 b01 = bp[0], b23 = bp[1];

    float2 fa01 = __half22float2(a01), fa23 = __half22float2(a23);
    float2 fb01 = __half22float2(b01), fb23 = __half22float2(b23);

    float4 v;
    v.x = fmaxf(fmaf(w, fa01.x, fb01.x), 0.f);
    v.y = fmaxf(fmaf(w, fa01.y, fb01.y), 0.f);
    v.z = fmaxf(fmaf(w, fa23.x, fb23.x), 0.f);
    v.w = fmaxf(fmaf(w, fa23.y, fb23.y), 0.f);

    atomicAdd((float4*)(g_H + (long long)col * C + lane * 4), v);
    if (lane == 0) atomicAdd(&g_deg[col], 1.0f);
}

// ---------------------------------------------------------------------------
// Phase 3 (tensor): out[n] = H[n] @ W2 + deg[n] * b2
// 128-node tile, 8 warps x m16, 8 n8 tiles (N=64), K=64 in two 32-wide stages.
// ---------------------------------------------------------------------------
__global__ __launch_bounds__(256) void phase3_kernel(
    float* __restrict__ out,
    const float* __restrict__ W2,
    const float* __restrict__ b2)
{
    __shared__ float hs[128][36];    // [node][k-local]
    __shared__ float ws2[32][72];    // [k-local][j 0..63], pad 72 -> banks 8t4+g

    const int t    = threadIdx.x;
    const int warp = t >> 5;
    const int lane = t & 31;
    const int gid  = lane >> 2;
    const int t4   = lane & 3;
    const int node0 = blockIdx.x * 128;

    float acc[8][4];
    #pragma unroll
    for (int nt = 0; nt < 8; nt++)
        #pragma unroll
        for (int q = 0; q < 4; q++) acc[nt][q] = 0.f;

    #pragma unroll 1
    for (int stage = 0; stage < 2; stage++) {
        const int ks0 = stage * 32;

        for (int i = t; i < 128 * 8; i += 256) {
            int n  = i >> 3;
            int kc = (i & 7) * 4;
            float4 v = make_float4(0.f, 0.f, 0.f, 0.f);
            int gn = node0 + n;
            if (gn < N_NODES) v = *(const float4*)(g_H + (long long)gn * C + ks0 + kc);
            hs[n][kc + 0] = round_tf32(v.x);
            hs[n][kc + 1] = round_tf32(v.y);
            hs[n][kc + 2] = round_tf32(v.z);
            hs[n][kc + 3] = round_tf32(v.w);
        }
        for (int i = t; i < 32 * 16; i += 256) {
            int k  = i >> 4;
            int jc = (i & 15) * 4;
            float4 v = *(const float4*)(W2 + (ks0 + k) * 64 + jc);
            ws2[k][jc + 0] = round_tf32(v.x);
            ws2[k][jc + 1] = round_tf32(v.y);
            ws2[k][jc + 2] = round_tf32(v.z);
            ws2[k][jc + 3] = round_tf32(v.w);
        }
        __syncthreads();

        const int m0 = warp * 16;
        #pragma unroll
        for (int slab = 0; slab < 4; slab++) {
            const int ks = slab * 8;
            unsigned a0 = __float_as_uint(hs[m0 + gid    ][ks + t4    ]);
            unsigned a1 = __float_as_uint(hs[m0 + gid + 8][ks + t4    ]);
            unsigned a2 = __float_as_uint(hs[m0 + gid    ][ks + t4 + 4]);
            unsigned a3 = __float_as_uint(hs[m0 + gid + 8][ks + t4 + 4]);
            #pragma unroll
            for (int nt = 0; nt < 8; nt++) {
                unsigned b0 = __float_as_uint(ws2[ks + t4    ][nt * 8 + gid]);
                unsigned b1 = __float_as_uint(ws2[ks + t4 + 4][nt * 8 + gid]);
                mma_tf32(acc[nt][0], acc[nt][1], acc[nt][2], acc[nt][3],
                         a0, a1, a2, a3, b0, b1);
            }
        }
        __syncthreads();
    }

    const int r0 = node0 + warp * 16 + gid;
    const int r1 = r0 + 8;
    const float d0 = (r0 < N_NODES) ? g_deg[r0] : 0.f;
    const float d1 = (r1 < N_NODES) ? g_deg[r1] : 0.f;
    #pragma unroll
    for (int nt = 0; nt < 8; nt++) {
        int col = nt * 8 + 2 * t4;
        float bx = b2[col], by = b2[col + 1];
        if (r0 < N_NODES) {
            float2 v = make_float2(acc[nt][0] + d0 * bx, acc[nt][1] + d0 * by);
            *(float2*)(out + (long long)r0 * C + col) = v;
        }
        if (r1 < N_NODES) {
            float2 v = make_float2(acc[nt][2] + d1 * bx, acc[nt][3] + d1 * by);
            *(float2*)(out + (long long)r1 * C + col) = v;
        }
    }
}

// ---------------------------------------------------------------------------
extern "C" void kernel_launch(void* const* d_in, const int* in_sizes, int n_in,
                              void* d_out, int out_size)
{
    const float* x  = (const float*)d_in[0];
    const void*  ei = (const void*)d_in[1];   // int32 or int64, detected on device
    const float* ea = (const float*)d_in[2];
    const float* W1 = (const float*)d_in[3];
    const float* b1 = (const float*)d_in[4];
    const float* W2 = (const float*)d_in[5];
    const float* b2 = (const float*)d_in[6];
    float* out = (float*)d_out;

    const int node_blocks = (N_NODES + 127) / 128;   // 782
    phase1_kernel<<<node_blocks, 256>>>(x, W1, b1, (const int*)ei);

    const int edge_blocks = (N_EDGES * 16) / 256;    // 50000, exact
    edge_kernel<<<edge_blocks, 256>>>(ei, ea);

    phase3_kernel<<<node_blocks, 256>>>(out, W2, b2);
}

// round 6
// speedup vs baseline: 1.5550x; 1.0366x over previous
#include <cuda_runtime.h>
#include <cuda_fp16.h>

#define N_NODES 100000
#define N_EDGES 800000
#define C 64

// Scratch (device globals — no allocation allowed)
__device__ __half g_A[N_NODES * C];   // fp16: x @ W1_top
__device__ __half g_B[N_NODES * C];   // fp16: x @ W1_bot + b1
__device__ float  g_H[N_NODES * C];   // fp32 scatter accumulator of relu(h)
__device__ float  g_deg[N_NODES];     // in-degree
__device__ int    g_is64;             // edge_index dtype flag

#define XS_PAD 68     // 68 % 32 = 4 -> banks 4*gid + t4, conflict-free
#define WS1_PAD 136   // 136 % 32 = 8 -> banks 8*t4 + gid, conflict-free
#define WS2_PAD 72    // 72 % 32 = 8 -> same

// ---- tf32 helpers -----------------------------------------------------------
__device__ __forceinline__ float round_tf32(float x) {
    unsigned u;
    asm("cvt.rna.tf32.f32 %0, %1;" : "=r"(u) : "f"(x));
    return __uint_as_float(u);
}

__device__ __forceinline__ void mma_tf32(
    float& c0, float& c1, float& c2, float& c3,
    unsigned a0, unsigned a1, unsigned a2, unsigned a3,
    unsigned b0, unsigned b1)
{
    asm volatile(
        "mma.sync.aligned.m16n8k8.row.col.f32.tf32.tf32.f32 "
        "{%0,%1,%2,%3},{%4,%5,%6,%7},{%8,%9},{%0,%1,%2,%3};"
        : "+f"(c0), "+f"(c1), "+f"(c2), "+f"(c3)
        : "r"(a0), "r"(a1), "r"(a2), "r"(a3), "r"(b0), "r"(b1));
}

// ---------------------------------------------------------------------------
// Phase 1 (tensor): g_A[n,:] = half(x[n] @ W1[0:64,:])
//                   g_B[n,:] = half(x[n] @ W1[64:128,:] + b1)
// 128-node tile, 512 threads = 16 warps. warp = (m-slab 0..7) x (n-half 0..1):
// each warp does m16 x n64 with 8 n8-tiles, K=64 in ONE stage (single barrier
// round). acc = 32 regs/thread. Also zeroes g_H/g_deg slice, writes dtype flag.
// Dynamic smem: xs[128][68] + ws[64][136] = 69632 B.
// ---------------------------------------------------------------------------
__global__ __launch_bounds__(512) void phase1_kernel(
    const float* __restrict__ x,
    const float* __restrict__ W1,
    const float* __restrict__ bias1,
    const int*   __restrict__ ei_probe)
{
    extern __shared__ float sm[];
    float (*xs)[XS_PAD]  = (float(*)[XS_PAD])sm;                  // 128 rows
    float (*ws)[WS1_PAD] = (float(*)[WS1_PAD])(sm + 128 * XS_PAD); // 64 rows

    const int t    = threadIdx.x;
    const int warp = t >> 5;
    const int lane = t & 31;
    const int gid  = lane >> 2;     // 0..7
    const int t4   = lane & 3;      // 0..3
    const int node0 = blockIdx.x * 128;
    const int m0   = (warp & 7) * 16;
    const int jb   = (warp >> 3) * 64;   // n-half: 0 -> A cols, 64 -> B cols

    if (blockIdx.x == 0 && t == 0) {
        g_is64 = ((ei_probe[1] | ei_probe[3] | ei_probe[5] | ei_probe[7] |
                   ei_probe[9] | ei_probe[11] | ei_probe[13] | ei_probe[15]) == 0);
    }

    // Zero this block's slice of g_H (128*64 floats) and g_deg.
    {
        const float4 z = make_float4(0.f, 0.f, 0.f, 0.f);
        long long base = (long long)node0 * C;
        for (int i = t; i < 128 * 16; i += 512) {
            long long off = base + (long long)i * 4;
            if (off < (long long)N_NODES * C) *(float4*)(g_H + off) = z;
        }
        for (int i = t; i < 128; i += 512) {
            int gn = node0 + i;
            if (gn < N_NODES) g_deg[gn] = 0.f;
        }
    }

    // Load X tile [128][64] tf32-rounded (4 float4 per thread).
    for (int i = t; i < 128 * 16; i += 512) {
        int n  = i >> 4;
        int kc = (i & 15) * 4;
        float4 v = make_float4(0.f, 0.f, 0.f, 0.f);
        int gn = node0 + n;
        if (gn < N_NODES) v = *(const float4*)(x + (long long)gn * C + kc);
        xs[n][kc + 0] = round_tf32(v.x);
        xs[n][kc + 1] = round_tf32(v.y);
        xs[n][kc + 2] = round_tf32(v.z);
        xs[n][kc + 3] = round_tf32(v.w);
    }
    // Load W tile [64][128]: j<64 -> W1[k][j] (A), j>=64 -> W1[64+k][j-64] (B).
    for (int i = t; i < 64 * 32; i += 512) {
        int k  = i >> 5;
        int jc = (i & 31) * 4;
        const float* src = (jc < 64) ? (W1 + k * 64 + jc)
                                     : (W1 + (64 + k) * 64 + (jc - 64));
        float4 v = *(const float4*)src;
        ws[k][jc + 0] = round_tf32(v.x);
        ws[k][jc + 1] = round_tf32(v.y);
        ws[k][jc + 2] = round_tf32(v.z);
        ws[k][jc + 3] = round_tf32(v.w);
    }
    __syncthreads();

    float acc[8][4];
    #pragma unroll
    for (int nt = 0; nt < 8; nt++)
        #pragma unroll
        for (int q = 0; q < 4; q++) acc[nt][q] = 0.f;

    #pragma unroll
    for (int slab = 0; slab < 8; slab++) {
        const int ks = slab * 8;
        unsigned a0 = __float_as_uint(xs[m0 + gid    ][ks + t4    ]);
        unsigned a1 = __float_as_uint(xs[m0 + gid + 8][ks + t4    ]);
        unsigned a2 = __float_as_uint(xs[m0 + gid    ][ks + t4 + 4]);
        unsigned a3 = __float_as_uint(xs[m0 + gid + 8][ks + t4 + 4]);
        #pragma unroll
        for (int nt = 0; nt < 8; nt++) {
            unsigned b0 = __float_as_uint(ws[ks + t4    ][jb + nt * 8 + gid]);
            unsigned b1 = __float_as_uint(ws[ks + t4 + 4][jb + nt * 8 + gid]);
            mma_tf32(acc[nt][0], acc[nt][1], acc[nt][2], acc[nt][3],
                     a0, a1, a2, a3, b0, b1);
        }
    }

    // Epilogue: c0,c1 -> (row gid, cols col..col+1); c2,c3 -> row gid+8.
    const int r0 = node0 + m0 + gid;
    const int r1 = r0 + 8;
    if (jb == 0) {
        #pragma unroll
        for (int nt = 0; nt < 8; nt++) {
            int col = nt * 8 + 2 * t4;
            if (r0 < N_NODES)
                *(__half2*)(g_A + (long long)r0 * C + col) = __floats2half2_rn(acc[nt][0], acc[nt][1]);
            if (r1 < N_NODES)
                *(__half2*)(g_A + (long long)r1 * C + col) = __floats2half2_rn(acc[nt][2], acc[nt][3]);
        }
    } else {
        #pragma unroll
        for (int nt = 0; nt < 8; nt++) {
            int col = nt * 8 + 2 * t4;
            float bx = bias1[col], by = bias1[col + 1];
            if (r0 < N_NODES)
                *(__half2*)(g_B + (long long)r0 * C + col) = __floats2half2_rn(acc[nt][0] + bx, acc[nt][1] + by);
            if (r1 < N_NODES)
                *(__half2*)(g_B + (long long)r1 * C + col) = __floats2half2_rn(acc[nt][2] + bx, acc[nt][3] + by);
        }
    }
}

// ---------------------------------------------------------------------------
// Phase 2 (edge): H[col] += relu(ea * A[row] + B[col]); deg[col] += 1
// 8 lanes per edge; 16B fp16 gathers, fp32 math, 2x float4 atomics.
// ---------------------------------------------------------------------------
__global__ __launch_bounds__(256) void edge_kernel(
    const void* __restrict__ ei_raw,
    const float* __restrict__ ea)
{
    const int tid = blockIdx.x * 256 + threadIdx.x;
    const int e = tid >> 3;
    if (e >= N_EDGES) return;
    const int lane = tid & 7;

    int row, col;
    if (g_is64) {
        const long long* e64 = (const long long*)ei_raw;
        row = (int)e64[e];
        col = (int)e64[N_EDGES + e];
    } else {
        const int* e32 = (const int*)ei_raw;
        row = e32[e];
        col = e32[N_EDGES + e];
    }
    const float w = ea[e];

    // 8 halves (16B) per lane from A[row] and B[col]
    uint4 au = *(const uint4*)(g_A + (long long)row * C + lane * 8);
    uint4 bu = *(const uint4*)(g_B + (long long)col * C + lane * 8);

    float2 a0 = __half22float2(*(__half2*)&au.x);
    float2 a1 = __half22float2(*(__half2*)&au.y);
    float2 a2 = __half22float2(*(__half2*)&au.z);
    float2 a3 = __half22float2(*(__half2*)&au.w);
    float2 b0 = __half22float2(*(__half2*)&bu.x);
    float2 b1 = __half22float2(*(__half2*)&bu.y);
    float2 b2v = __half22float2(*(__half2*)&bu.z);
    float2 b3 = __half22float2(*(__half2*)&bu.w);

    float4 v0, v1;
    v0.x = fmaxf(fmaf(w, a0.x, b0.x), 0.f);
    v0.y = fmaxf(fmaf(w, a0.y, b0.y), 0.f);
    v0.z = fmaxf(fmaf(w, a1.x, b1.x), 0.f);
    v0.w = fmaxf(fmaf(w, a1.y, b1.y), 0.f);
    v1.x = fmaxf(fmaf(w, a2.x, b2v.x), 0.f);
    v1.y = fmaxf(fmaf(w, a2.y, b2v.y), 0.f);
    v1.z = fmaxf(fmaf(w, a3.x, b3.x), 0.f);
    v1.w = fmaxf(fmaf(w, a3.y, b3.y), 0.f);

    float* hp = g_H + (long long)col * C + lane * 8;
    atomicAdd((float4*)hp, v0);
    atomicAdd((float4*)(hp + 4), v1);
    if (lane == 0) atomicAdd(&g_deg[col], 1.0f);
}

// ---------------------------------------------------------------------------
// Phase 3 (tensor): out[n] = H[n] @ W2 + deg[n] * b2
// 128-node tile, 512 threads; warp = (m-slab 0..7) x (n-half 0..1),
// each warp m16 x n32 (4 n8-tiles), K=64 single stage. acc = 16 regs.
// Dynamic smem: hs[128][68] + ws2[64][72] = 53248 B.
// ---------------------------------------------------------------------------
__global__ __launch_bounds__(512) void phase3_kernel(
    float* __restrict__ out,
    const float* __restrict__ W2,
    const float* __restrict__ b2)
{
    extern __shared__ float sm[];
    float (*hs)[XS_PAD]  = (float(*)[XS_PAD])sm;
    float (*ws2)[WS2_PAD] = (float(*)[WS2_PAD])(sm + 128 * XS_PAD);

    const int t    = threadIdx.x;
    const int warp = t >> 5;
    const int lane = t & 31;
    const int gid  = lane >> 2;
    const int t4   = lane & 3;
    const int node0 = blockIdx.x * 128;
    const int m0   = (warp & 7) * 16;
    const int jb   = (warp >> 3) * 32;

    for (int i = t; i < 128 * 16; i += 512) {
        int n  = i >> 4;
        int kc = (i & 15) * 4;
        float4 v = make_float4(0.f, 0.f, 0.f, 0.f);
        int gn = node0 + n;
        if (gn < N_NODES) v = *(const float4*)(g_H + (long long)gn * C + kc);
        hs[n][kc + 0] = round_tf32(v.x);
        hs[n][kc + 1] = round_tf32(v.y);
        hs[n][kc + 2] = round_tf32(v.z);
        hs[n][kc + 3] = round_tf32(v.w);
    }
    for (int i = t; i < 64 * 16; i += 512) {
        int k  = i >> 4;
        int jc = (i & 15) * 4;
        float4 v = *(const float4*)(W2 + k * 64 + jc);
        ws2[k][jc + 0] = round_tf32(v.x);
        ws2[k][jc + 1] = round_tf32(v.y);
        ws2[k][jc + 2] = round_tf32(v.z);
        ws2[k][jc + 3] = round_tf32(v.w);
    }
    __syncthreads();

    float acc[4][4];
    #pragma unroll
    for (int nt = 0; nt < 4; nt++)
        #pragma unroll
        for (int q = 0; q < 4; q++) acc[nt][q] = 0.f;

    #pragma unroll
    for (int slab = 0; slab < 8; slab++) {
        const int ks = slab * 8;
        unsigned a0 = __float_as_uint(hs[m0 + gid    ][ks + t4    ]);
        unsigned a1 = __float_as_uint(hs[m0 + gid + 8][ks + t4    ]);
        unsigned a2 = __float_as_uint(hs[m0 + gid    ][ks + t4 + 4]);
        unsigned a3 = __float_as_uint(hs[m0 + gid + 8][ks + t4 + 4]);
        #pragma unroll
        for (int nt = 0; nt < 4; nt++) {
            unsigned b0 = __float_as_uint(ws2[ks + t4    ][jb + nt * 8 + gid]);
            unsigned b1 = __float_as_uint(ws2[ks + t4 + 4][jb + nt * 8 + gid]);
            mma_tf32(acc[nt][0], acc[nt][1], acc[nt][2], acc[nt][3],
                     a0, a1, a2, a3, b0, b1);
        }
    }

    const int r0 = node0 + m0 + gid;
    const int r1 = r0 + 8;
    const float d0 = (r0 < N_NODES) ? g_deg[r0] : 0.f;
    const float d1 = (r1 < N_NODES) ? g_deg[r1] : 0.f;
    #pragma unroll
    for (int nt = 0; nt < 4; nt++) {
        int col = jb + nt * 8 + 2 * t4;
        float bx = b2[col], by = b2[col + 1];
        if (r0 < N_NODES) {
            float2 v = make_float2(acc[nt][0] + d0 * bx, acc[nt][1] + d0 * by);
            *(float2*)(out + (long long)r0 * C + col) = v;
        }
        if (r1 < N_NODES) {
            float2 v = make_float2(acc[nt][2] + d1 * bx, acc[nt][3] + d1 * by);
            *(float2*)(out + (long long)r1 * C + col) = v;
        }
    }
}

// ---------------------------------------------------------------------------
extern "C" void kernel_launch(void* const* d_in, const int* in_sizes, int n_in,
                              void* d_out, int out_size)
{
    const float* x  = (const float*)d_in[0];
    const void*  ei = (const void*)d_in[1];   // int32 or int64, detected on device
    const float* ea = (const float*)d_in[2];
    const float* W1 = (const float*)d_in[3];
    const float* b1 = (const float*)d_in[4];
    const float* W2 = (const float*)d_in[5];
    const float* b2 = (const float*)d_in[6];
    float* out = (float*)d_out;

    const int smem1 = (128 * XS_PAD + 64 * WS1_PAD) * 4;   // 69632
    const int smem3 = (128 * XS_PAD + 64 * WS2_PAD) * 4;   // 53248
    cudaFuncSetAttribute(phase1_kernel, cudaFuncAttributeMaxDynamicSharedMemorySize, smem1);
    cudaFuncSetAttribute(phase3_kernel, cudaFuncAttributeMaxDynamicSharedMemorySize, smem3);

    const int node_blocks = (N_NODES + 127) / 128;   // 782
    phase1_kernel<<<node_blocks, 512, smem1>>>(x, W1, b1, (const int*)ei);

    const int edge_blocks = (N_EDGES * 8) / 256;     // 25000, exact
    edge_kernel<<<edge_blocks, 256>>>(ei, ea);

    phase3_kernel<<<node_blocks, 512, smem3>>>(out, W2, b2);
}

// round 7
// speedup vs baseline: 1.6380x; 1.0534x over previous
#include <cuda_runtime.h>
#include <cuda_fp16.h>

#define N_NODES 100000
#define N_EDGES 800000
#define C 64

// Scratch (device globals — no allocation allowed)
__device__ __half g_A[N_NODES * C];    // fp16: x @ W1_top
__device__ __half g_B[N_NODES * C];    // fp16: x @ W1_bot + b1
__device__ float  g_H[N_NODES * C];    // per-node accumulated relu(h) (non-atomic)
__device__ int    g_cnt[N_NODES];      // in-degree (histogram)
__device__ int    g_start[N_NODES];    // CSR row start
__device__ int    g_cursor[N_NODES];   // scatter cursors
__device__ int    g_bsum[128];         // scan block sums
__device__ int    g_boff[128];         // scan block offsets
__device__ uint2  g_edat[N_EDGES];     // dest-sorted (row, w-bits)
__device__ int    g_is64;              // edge_index dtype flag

#define XS_PAD 68     // 68 % 32 = 4 -> banks 4*gid + t4, conflict-free
#define WS1_PAD 136   // 136 % 32 = 8 -> banks 8*t4 + gid, conflict-free
#define WS2_PAD 72

// ---- tf32 helpers -----------------------------------------------------------
__device__ __forceinline__ float round_tf32(float x) {
    unsigned u;
    asm("cvt.rna.tf32.f32 %0, %1;" : "=r"(u) : "f"(x));
    return __uint_as_float(u);
}

__device__ __forceinline__ void mma_tf32(
    float& c0, float& c1, float& c2, float& c3,
    unsigned a0, unsigned a1, unsigned a2, unsigned a3,
    unsigned b0, unsigned b1)
{
    asm volatile(
        "mma.sync.aligned.m16n8k8.row.col.f32.tf32.tf32.f32 "
        "{%0,%1,%2,%3},{%4,%5,%6,%7},{%8,%9},{%0,%1,%2,%3};"
        : "+f"(c0), "+f"(c1), "+f"(c2), "+f"(c3)
        : "r"(a0), "r"(a1), "r"(a2), "r"(a3), "r"(b0), "r"(b1));
}

// ---------------------------------------------------------------------------
// Phase 1 (tensor): g_A = half(x @ W1_top), g_B = half(x @ W1_bot + b1)
// 128-node tile, 512 threads = 16 warps; warp = (m-slab) x (n-half). K=64,
// single barrier round. Writes the dtype flag.
// ---------------------------------------------------------------------------
__global__ __launch_bounds__(512) void phase1_kernel(
    const float* __restrict__ x,
    const float* __restrict__ W1,
    const float* __restrict__ bias1,
    const int*   __restrict__ ei_probe)
{
    extern __shared__ float sm[];
    float (*xs)[XS_PAD]  = (float(*)[XS_PAD])sm;
    float (*ws)[WS1_PAD] = (float(*)[WS1_PAD])(sm + 128 * XS_PAD);

    const int t    = threadIdx.x;
    const int warp = t >> 5;
    const int lane = t & 31;
    const int gid  = lane >> 2;
    const int t4   = lane & 3;
    const int node0 = blockIdx.x * 128;
    const int m0   = (warp & 7) * 16;
    const int jb   = (warp >> 3) * 64;

    if (blockIdx.x == 0 && t == 0) {
        g_is64 = ((ei_probe[1] | ei_probe[3] | ei_probe[5] | ei_probe[7] |
                   ei_probe[9] | ei_probe[11] | ei_probe[13] | ei_probe[15]) == 0);
    }

    for (int i = t; i < 128 * 16; i += 512) {
        int n  = i >> 4;
        int kc = (i & 15) * 4;
        float4 v = make_float4(0.f, 0.f, 0.f, 0.f);
        int gn = node0 + n;
        if (gn < N_NODES) v = *(const float4*)(x + (long long)gn * C + kc);
        xs[n][kc + 0] = round_tf32(v.x);
        xs[n][kc + 1] = round_tf32(v.y);
        xs[n][kc + 2] = round_tf32(v.z);
        xs[n][kc + 3] = round_tf32(v.w);
    }
    for (int i = t; i < 64 * 32; i += 512) {
        int k  = i >> 5;
        int jc = (i & 31) * 4;
        const float* src = (jc < 64) ? (W1 + k * 64 + jc)
                                     : (W1 + (64 + k) * 64 + (jc - 64));
        float4 v = *(const float4*)src;
        ws[k][jc + 0] = round_tf32(v.x);
        ws[k][jc + 1] = round_tf32(v.y);
        ws[k][jc + 2] = round_tf32(v.z);
        ws[k][jc + 3] = round_tf32(v.w);
    }
    __syncthreads();

    float acc[8][4];
    #pragma unroll
    for (int nt = 0; nt < 8; nt++)
        #pragma unroll
        for (int q = 0; q < 4; q++) acc[nt][q] = 0.f;

    #pragma unroll
    for (int slab = 0; slab < 8; slab++) {
        const int ks = slab * 8;
        unsigned a0 = __float_as_uint(xs[m0 + gid    ][ks + t4    ]);
        unsigned a1 = __float_as_uint(xs[m0 + gid + 8][ks + t4    ]);
        unsigned a2 = __float_as_uint(xs[m0 + gid    ][ks + t4 + 4]);
        unsigned a3 = __float_as_uint(xs[m0 + gid + 8][ks + t4 + 4]);
        #pragma unroll
        for (int nt = 0; nt < 8; nt++) {
            unsigned b0 = __float_as_uint(ws[ks + t4    ][jb + nt * 8 + gid]);
            unsigned b1 = __float_as_uint(ws[ks + t4 + 4][jb + nt * 8 + gid]);
            mma_tf32(acc[nt][0], acc[nt][1], acc[nt][2], acc[nt][3],
                     a0, a1, a2, a3, b0, b1);
        }
    }

    const int r0 = node0 + m0 + gid;
    const int r1 = r0 + 8;
    if (jb == 0) {
        #pragma unroll
        for (int nt = 0; nt < 8; nt++) {
            int col = nt * 8 + 2 * t4;
            if (r0 < N_NODES)
                *(__half2*)(g_A + (long long)r0 * C + col) = __floats2half2_rn(acc[nt][0], acc[nt][1]);
            if (r1 < N_NODES)
                *(__half2*)(g_A + (long long)r1 * C + col) = __floats2half2_rn(acc[nt][2], acc[nt][3]);
        }
    } else {
        #pragma unroll
        for (int nt = 0; nt < 8; nt++) {
            int col = nt * 8 + 2 * t4;
            float bx = bias1[col], by = bias1[col + 1];
            if (r0 < N_NODES)
                *(__half2*)(g_B + (long long)r0 * C + col) = __floats2half2_rn(acc[nt][0] + bx, acc[nt][1] + by);
            if (r1 < N_NODES)
                *(__half2*)(g_B + (long long)r1 * C + col) = __floats2half2_rn(acc[nt][2] + bx, acc[nt][3] + by);
        }
    }
}

// ---------------------------------------------------------------------------
// CSR build: histogram, 3-step exclusive scan, scatter (row, w) by dest.
// ---------------------------------------------------------------------------
__global__ __launch_bounds__(256) void hist_kernel(const void* __restrict__ ei_raw)
{
    const int e = blockIdx.x * 256 + threadIdx.x;
    if (e >= N_EDGES) return;
    int col;
    if (g_is64) col = (int)((const long long*)ei_raw)[N_EDGES + e];
    else        col = ((const int*)ei_raw)[N_EDGES + e];
    atomicAdd(&g_cnt[col], 1);
}

__global__ __launch_bounds__(1024) void scanA_kernel()
{
    __shared__ int s[1024];
    const int tid = threadIdx.x;
    const int gid = blockIdx.x * 1024 + tid;
    int v = (gid < N_NODES) ? g_cnt[gid] : 0;
    s[tid] = v;
    __syncthreads();
    #pragma unroll
    for (int off = 1; off < 1024; off <<= 1) {
        int add = (tid >= off) ? s[tid - off] : 0;
        __syncthreads();
        s[tid] += add;
        __syncthreads();
    }
    if (gid < N_NODES) g_start[gid] = s[tid] - v;   // exclusive
    if (tid == 1023) g_bsum[blockIdx.x] = s[1023];
}

__global__ void scanB_kernel(int nblocks)
{
    if (threadIdx.x == 0) {
        int run = 0;
        for (int b = 0; b < nblocks; b++) { g_boff[b] = run; run += g_bsum[b]; }
    }
}

__global__ __launch_bounds__(1024) void scanC_kernel()
{
    const int gid = blockIdx.x * 1024 + threadIdx.x;
    if (gid >= N_NODES) return;
    int st = g_start[gid] + g_boff[blockIdx.x];
    g_start[gid] = st;
    g_cursor[gid] = st;
}

__global__ __launch_bounds__(256) void scatter_kernel(
    const void* __restrict__ ei_raw,
    const float* __restrict__ ea)
{
    const int e = blockIdx.x * 256 + threadIdx.x;
    if (e >= N_EDGES) return;
    int row, col;
    if (g_is64) {
        const long long* e64 = (const long long*)ei_raw;
        row = (int)e64[e];
        col = (int)e64[N_EDGES + e];
    } else {
        const int* e32 = (const int*)ei_raw;
        row = e32[e];
        col = e32[N_EDGES + e];
    }
    int pos = atomicAdd(&g_cursor[col], 1);
    g_edat[pos] = make_uint2((unsigned)row, __float_as_uint(ea[e]));
}

// ---------------------------------------------------------------------------
// Gather (replaces atomic edge kernel): warp per node.
// Lane owns 2 channels (half2 = 4B). B[col] loaded once; per edge a broadcast
// (row,w) read + one coalesced 128B A-row gather; relu-accumulate in fp32;
// one non-atomic H row store. Unrolled x4 for MLP.
// ---------------------------------------------------------------------------
__global__ __launch_bounds__(256) void gather_kernel()
{
    const int wg = (blockIdx.x * 256 + threadIdx.x) >> 5;
    if (wg >= N_NODES) return;
    const int lane = threadIdx.x & 31;

    const int start = g_start[wg];
    const int cnt   = g_cnt[wg];

    float2 bf = __half22float2(*(const __half2*)(g_B + (long long)wg * C + lane * 2));
    float2 acc = make_float2(0.f, 0.f);

    int i = 0;
    for (; i + 4 <= cnt; i += 4) {
        uint2 d0 = g_edat[start + i];
        uint2 d1 = g_edat[start + i + 1];
        uint2 d2 = g_edat[start + i + 2];
        uint2 d3 = g_edat[start + i + 3];
        __half2 a0 = *(const __half2*)(g_A + (long long)d0.x * C + lane * 2);
        __half2 a1 = *(const __half2*)(g_A + (long long)d1.x * C + lane * 2);
        __half2 a2 = *(const __half2*)(g_A + (long long)d2.x * C + lane * 2);
        __half2 a3 = *(const __half2*)(g_A + (long long)d3.x * C + lane * 2);
        float2 f0 = __half22float2(a0), f1 = __half22float2(a1);
        float2 f2 = __half22float2(a2), f3 = __half22float2(a3);
        float w0 = __uint_as_float(d0.y), w1 = __uint_as_float(d1.y);
        float w2 = __uint_as_float(d2.y), w3 = __uint_as_float(d3.y);
        acc.x += fmaxf(fmaf(w0, f0.x, bf.x), 0.f);
        acc.y += fmaxf(fmaf(w0, f0.y, bf.y), 0.f);
        acc.x += fmaxf(fmaf(w1, f1.x, bf.x), 0.f);
        acc.y += fmaxf(fmaf(w1, f1.y, bf.y), 0.f);
        acc.x += fmaxf(fmaf(w2, f2.x, bf.x), 0.f);
        acc.y += fmaxf(fmaf(w2, f2.y, bf.y), 0.f);
        acc.x += fmaxf(fmaf(w3, f3.x, bf.x), 0.f);
        acc.y += fmaxf(fmaf(w3, f3.y, bf.y), 0.f);
    }
    for (; i < cnt; i++) {
        uint2 d = g_edat[start + i];
        float2 f = __half22float2(*(const __half2*)(g_A + (long long)d.x * C + lane * 2));
        float w = __uint_as_float(d.y);
        acc.x += fmaxf(fmaf(w, f.x, bf.x), 0.f);
        acc.y += fmaxf(fmaf(w, f.y, bf.y), 0.f);
    }

    *(float2*)(g_H + (long long)wg * C + lane * 2) = acc;
}

// ---------------------------------------------------------------------------
// Phase 3 (tensor): out[n] = H[n] @ W2 + cnt[n] * b2
// ---------------------------------------------------------------------------
__global__ __launch_bounds__(512) void phase3_kernel(
    float* __restrict__ out,
    const float* __restrict__ W2,
    const float* __restrict__ b2)
{
    extern __shared__ float sm[];
    float (*hs)[XS_PAD]   = (float(*)[XS_PAD])sm;
    float (*ws2)[WS2_PAD] = (float(*)[WS2_PAD])(sm + 128 * XS_PAD);

    const int t    = threadIdx.x;
    const int warp = t >> 5;
    const int lane = t & 31;
    const int gid  = lane >> 2;
    const int t4   = lane & 3;
    const int node0 = blockIdx.x * 128;
    const int m0   = (warp & 7) * 16;
    const int jb   = (warp >> 3) * 32;

    for (int i = t; i < 128 * 16; i += 512) {
        int n  = i >> 4;
        int kc = (i & 15) * 4;
        float4 v = make_float4(0.f, 0.f, 0.f, 0.f);
        int gn = node0 + n;
        if (gn < N_NODES) v = *(const float4*)(g_H + (long long)gn * C + kc);
        hs[n][kc + 0] = round_tf32(v.x);
        hs[n][kc + 1] = round_tf32(v.y);
        hs[n][kc + 2] = round_tf32(v.z);
        hs[n][kc + 3] = round_tf32(v.w);
    }
    for (int i = t; i < 64 * 16; i += 512) {
        int k  = i >> 4;
        int jc = (i & 15) * 4;
        float4 v = *(const float4*)(W2 + k * 64 + jc);
        ws2[k][jc + 0] = round_tf32(v.x);
        ws2[k][jc + 1] = round_tf32(v.y);
        ws2[k][jc + 2] = round_tf32(v.z);
        ws2[k][jc + 3] = round_tf32(v.w);
    }
    __syncthreads();

    float acc[4][4];
    #pragma unroll
    for (int nt = 0; nt < 4; nt++)
        #pragma unroll
        for (int q = 0; q < 4; q++) acc[nt][q] = 0.f;

    #pragma unroll
    for (int slab = 0; slab < 8; slab++) {
        const int ks = slab * 8;
        unsigned a0 = __float_as_uint(hs[m0 + gid    ][ks + t4    ]);
        unsigned a1 = __float_as_uint(hs[m0 + gid + 8][ks + t4    ]);
        unsigned a2 = __float_as_uint(hs[m0 + gid    ][ks + t4 + 4]);
        unsigned a3 = __float_as_uint(hs[m0 + gid + 8][ks + t4 + 4]);
        #pragma unroll
        for (int nt = 0; nt < 4; nt++) {
            unsigned b0 = __float_as_uint(ws2[ks + t4    ][jb + nt * 8 + gid]);
            unsigned b1 = __float_as_uint(ws2[ks + t4 + 4][jb + nt * 8 + gid]);
            mma_tf32(acc[nt][0], acc[nt][1], acc[nt][2], acc[nt][3],
                     a0, a1, a2, a3, b0, b1);
        }
    }

    const int r0 = node0 + m0 + gid;
    const int r1 = r0 + 8;
    const float d0 = (r0 < N_NODES) ? (float)g_cnt[r0] : 0.f;
    const float d1 = (r1 < N_NODES) ? (float)g_cnt[r1] : 0.f;
    #pragma unroll
    for (int nt = 0; nt < 4; nt++) {
        int col = jb + nt * 8 + 2 * t4;
        float bx = b2[col], by = b2[col + 1];
        if (r0 < N_NODES) {
            float2 v = make_float2(acc[nt][0] + d0 * bx, acc[nt][1] + d0 * by);
            *(float2*)(out + (long long)r0 * C + col) = v;
        }
        if (r1 < N_NODES) {
            float2 v = make_float2(acc[nt][2] + d1 * bx, acc[nt][3] + d1 * by);
            *(float2*)(out + (long long)r1 * C + col) = v;
        }
    }
}

// ---------------------------------------------------------------------------
extern "C" void kernel_launch(void* const* d_in, const int* in_sizes, int n_in,
                              void* d_out, int out_size)
{
    const float* x  = (const float*)d_in[0];
    const void*  ei = (const void*)d_in[1];   // int32 or int64, detected on device
    const float* ea = (const float*)d_in[2];
    const float* W1 = (const float*)d_in[3];
    const float* b1 = (const float*)d_in[4];
    const float* W2 = (const float*)d_in[5];
    const float* b2 = (const float*)d_in[6];
    float* out = (float*)d_out;

    void* cntp;
    cudaGetSymbolAddress(&cntp, g_cnt);
    cudaMemsetAsync(cntp, 0, (size_t)N_NODES * sizeof(int));

    const int smem1 = (128 * XS_PAD + 64 * WS1_PAD) * 4;   // 69632
    const int smem3 = (128 * XS_PAD + 64 * WS2_PAD) * 4;   // 53248
    cudaFuncSetAttribute(phase1_kernel, cudaFuncAttributeMaxDynamicSharedMemorySize, smem1);
    cudaFuncSetAttribute(phase3_kernel, cudaFuncAttributeMaxDynamicSharedMemorySize, smem3);

    const int node_blocks = (N_NODES + 127) / 128;     // 782
    const int edge_blocks = (N_EDGES + 255) / 256;     // 3125
    const int scan_blocks = (N_NODES + 1023) / 1024;   // 98

    phase1_kernel<<<node_blocks, 512, smem1>>>(x, W1, b1, (const int*)ei);
    hist_kernel<<<edge_blocks, 256>>>(ei);
    scanA_kernel<<<scan_blocks, 1024>>>();
    scanB_kernel<<<1, 32>>>(scan_blocks);
    scanC_kernel<<<scan_blocks, 1024>>>();
    scatter_kernel<<<edge_blocks, 256>>>(ei, ea);
    gather_kernel<<<(N_NODES * 32 + 255) / 256, 256>>>();
    phase3_kernel<<<node_blocks, 512, smem3>>>(out, W2, b2);
}

// round 8
// speedup vs baseline: 1.7854x; 1.0899x over previous
#include <cuda_runtime.h>
#include <cuda_fp16.h>

#define N_NODES 100000
#define N_EDGES 800000
#define C 64

// Scratch (device globals — no allocation allowed)
__device__ __half g_A[N_NODES * C];    // fp16: x @ W1_top
__device__ __half g_B[N_NODES * C];    // fp16: x @ W1_bot + b1
__device__ int    g_cnt[N_NODES];      // in-degree (histogram)
__device__ int    g_start[N_NODES];    // CSR row start
__device__ int    g_cursor[N_NODES];   // scatter cursors
__device__ int    g_bsum[128];         // scan block sums
__device__ uint2  g_edat[N_EDGES];     // dest-sorted (row, w-bits)
__device__ int    g_is64;              // edge_index dtype flag

#define XS_PAD 68     // 68 % 32 = 4 -> banks 4*gid + t4, conflict-free
#define WS1_PAD 136   // 136 % 32 = 8 -> banks 8*t4 + gid, conflict-free
#define WS2_PAD 72

// ---- tf32 helpers -----------------------------------------------------------
__device__ __forceinline__ float round_tf32(float x) {
    unsigned u;
    asm("cvt.rna.tf32.f32 %0, %1;" : "=r"(u) : "f"(x));
    return __uint_as_float(u);
}

__device__ __forceinline__ void mma_tf32(
    float& c0, float& c1, float& c2, float& c3,
    unsigned a0, unsigned a1, unsigned a2, unsigned a3,
    unsigned b0, unsigned b1)
{
    asm volatile(
        "mma.sync.aligned.m16n8k8.row.col.f32.tf32.tf32.f32 "
        "{%0,%1,%2,%3},{%4,%5,%6,%7},{%8,%9},{%0,%1,%2,%3};"
        : "+f"(c0), "+f"(c1), "+f"(c2), "+f"(c3)
        : "r"(a0), "r"(a1), "r"(a2), "r"(a3), "r"(b0), "r"(b1));
}

// ---------------------------------------------------------------------------
// Phase 1 (tensor): g_A = half(x @ W1_top), g_B = half(x @ W1_bot + b1)
// 128-node tile, 512 threads = 16 warps; warp = (m-slab) x (n-half). K=64,
// single barrier round. Writes the dtype flag.
// ---------------------------------------------------------------------------
__global__ __launch_bounds__(512) void phase1_kernel(
    const float* __restrict__ x,
    const float* __restrict__ W1,
    const float* __restrict__ bias1,
    const int*   __restrict__ ei_probe)
{
    extern __shared__ float sm[];
    float (*xs)[XS_PAD]  = (float(*)[XS_PAD])sm;
    float (*ws)[WS1_PAD] = (float(*)[WS1_PAD])(sm + 128 * XS_PAD);

    const int t    = threadIdx.x;
    const int warp = t >> 5;
    const int lane = t & 31;
    const int gid  = lane >> 2;
    const int t4   = lane & 3;
    const int node0 = blockIdx.x * 128;
    const int m0   = (warp & 7) * 16;
    const int jb   = (warp >> 3) * 64;

    if (blockIdx.x == 0 && t == 0) {
        g_is64 = ((ei_probe[1] | ei_probe[3] | ei_probe[5] | ei_probe[7] |
                   ei_probe[9] | ei_probe[11] | ei_probe[13] | ei_probe[15]) == 0);
    }

    for (int i = t; i < 128 * 16; i += 512) {
        int n  = i >> 4;
        int kc = (i & 15) * 4;
        float4 v = make_float4(0.f, 0.f, 0.f, 0.f);
        int gn = node0 + n;
        if (gn < N_NODES) v = *(const float4*)(x + (long long)gn * C + kc);
        xs[n][kc + 0] = round_tf32(v.x);
        xs[n][kc + 1] = round_tf32(v.y);
        xs[n][kc + 2] = round_tf32(v.z);
        xs[n][kc + 3] = round_tf32(v.w);
    }
    for (int i = t; i < 64 * 32; i += 512) {
        int k  = i >> 5;
        int jc = (i & 31) * 4;
        const float* src = (jc < 64) ? (W1 + k * 64 + jc)
                                     : (W1 + (64 + k) * 64 + (jc - 64));
        float4 v = *(const float4*)src;
        ws[k][jc + 0] = round_tf32(v.x);
        ws[k][jc + 1] = round_tf32(v.y);
        ws[k][jc + 2] = round_tf32(v.z);
        ws[k][jc + 3] = round_tf32(v.w);
    }
    __syncthreads();

    float acc[8][4];
    #pragma unroll
    for (int nt = 0; nt < 8; nt++)
        #pragma unroll
        for (int q = 0; q < 4; q++) acc[nt][q] = 0.f;

    #pragma unroll
    for (int slab = 0; slab < 8; slab++) {
        const int ks = slab * 8;
        unsigned a0 = __float_as_uint(xs[m0 + gid    ][ks + t4    ]);
        unsigned a1 = __float_as_uint(xs[m0 + gid + 8][ks + t4    ]);
        unsigned a2 = __float_as_uint(xs[m0 + gid    ][ks + t4 + 4]);
        unsigned a3 = __float_as_uint(xs[m0 + gid + 8][ks + t4 + 4]);
        #pragma unroll
        for (int nt = 0; nt < 8; nt++) {
            unsigned b0 = __float_as_uint(ws[ks + t4    ][jb + nt * 8 + gid]);
            unsigned b1 = __float_as_uint(ws[ks + t4 + 4][jb + nt * 8 + gid]);
            mma_tf32(acc[nt][0], acc[nt][1], acc[nt][2], acc[nt][3],
                     a0, a1, a2, a3, b0, b1);
        }
    }

    const int r0 = node0 + m0 + gid;
    const int r1 = r0 + 8;
    if (jb == 0) {
        #pragma unroll
        for (int nt = 0; nt < 8; nt++) {
            int col = nt * 8 + 2 * t4;
            if (r0 < N_NODES)
                *(__half2*)(g_A + (long long)r0 * C + col) = __floats2half2_rn(acc[nt][0], acc[nt][1]);
            if (r1 < N_NODES)
                *(__half2*)(g_A + (long long)r1 * C + col) = __floats2half2_rn(acc[nt][2], acc[nt][3]);
        }
    } else {
        #pragma unroll
        for (int nt = 0; nt < 8; nt++) {
            int col = nt * 8 + 2 * t4;
            float bx = bias1[col], by = bias1[col + 1];
            if (r0 < N_NODES)
                *(__half2*)(g_B + (long long)r0 * C + col) = __floats2half2_rn(acc[nt][0] + bx, acc[nt][1] + by);
            if (r1 < N_NODES)
                *(__half2*)(g_B + (long long)r1 * C + col) = __floats2half2_rn(acc[nt][2] + bx, acc[nt][3] + by);
        }
    }
}

// ---------------------------------------------------------------------------
// CSR build: histogram, scan (2 kernels), scatter (row, w) by dest.
// ---------------------------------------------------------------------------
__global__ __launch_bounds__(256) void hist_kernel(const void* __restrict__ ei_raw)
{
    const int e = blockIdx.x * 256 + threadIdx.x;
    if (e >= N_EDGES) return;
    int col;
    if (g_is64) col = (int)((const long long*)ei_raw)[N_EDGES + e];
    else        col = ((const int*)ei_raw)[N_EDGES + e];
    atomicAdd(&g_cnt[col], 1);
}

__global__ __launch_bounds__(1024) void scanA_kernel()
{
    __shared__ int s[1024];
    const int tid = threadIdx.x;
    const int gid = blockIdx.x * 1024 + tid;
    int v = (gid < N_NODES) ? g_cnt[gid] : 0;
    s[tid] = v;
    __syncthreads();
    #pragma unroll
    for (int off = 1; off < 1024; off <<= 1) {
        int add = (tid >= off) ? s[tid - off] : 0;
        __syncthreads();
        s[tid] += add;
        __syncthreads();
    }
    if (gid < N_NODES) g_start[gid] = s[tid] - v;   // exclusive within block
    if (tid == 1023) g_bsum[blockIdx.x] = s[1023];
}

// scanC with fused block-offset reduction: warp 0 sums g_bsum[0..b-1].
__global__ __launch_bounds__(1024) void scanC_kernel()
{
    __shared__ int s_off;
    const int tid = threadIdx.x;
    if (tid < 32) {
        int acc = 0;
        for (int i = tid; i < blockIdx.x; i += 32) acc += g_bsum[i];
        #pragma unroll
        for (int o = 16; o > 0; o >>= 1)
            acc += __shfl_down_sync(0xFFFFFFFF, acc, o);
        if (tid == 0) s_off = acc;
    }
    __syncthreads();
    const int gid = blockIdx.x * 1024 + tid;
    if (gid >= N_NODES) return;
    int st = g_start[gid] + s_off;
    g_start[gid] = st;
    g_cursor[gid] = st;
}

__global__ __launch_bounds__(256) void scatter_kernel(
    const void* __restrict__ ei_raw,
    const float* __restrict__ ea)
{
    const int e = blockIdx.x * 256 + threadIdx.x;
    if (e >= N_EDGES) return;
    int row, col;
    if (g_is64) {
        const long long* e64 = (const long long*)ei_raw;
        row = (int)e64[e];
        col = (int)e64[N_EDGES + e];
    } else {
        const int* e32 = (const int*)ei_raw;
        row = e32[e];
        col = e32[N_EDGES + e];
    }
    int pos = atomicAdd(&g_cursor[col], 1);
    g_edat[pos] = make_uint2((unsigned)row, __float_as_uint(ea[e]));
}

// ---------------------------------------------------------------------------
// Fused gather + phase 3: block of 512 threads handles 128 nodes.
// Step A: each of 16 warps gathers 8 nodes' relu-accumulated messages straight
//         into the hs smem tile (tf32-rounded). Lane owns 2 channels.
// Step B: tensor-core MMA  out[n] = hs[n] @ W2 + cnt[n] * b2.
// No g_H global round-trip.
// ---------------------------------------------------------------------------
__global__ __launch_bounds__(512) void phase23_kernel(
    float* __restrict__ out,
    const float* __restrict__ W2,
    const float* __restrict__ b2)
{
    extern __shared__ float sm[];
    float (*hs)[XS_PAD]   = (float(*)[XS_PAD])sm;
    float (*ws2)[WS2_PAD] = (float(*)[WS2_PAD])(sm + 128 * XS_PAD);

    const int t    = threadIdx.x;
    const int warp = t >> 5;
    const int lane = t & 31;
    const int node0 = blockIdx.x * 128;

    // ---- Step A: gather into smem ----
    #pragma unroll 1
    for (int j = 0; j < 8; j++) {
        const int nl = warp * 8 + j;        // local node 0..127
        const int gn = node0 + nl;
        float2 acc = make_float2(0.f, 0.f);
        if (gn < N_NODES) {
            const int start = g_start[gn];
            const int cnt   = g_cnt[gn];
            float2 bf = __half22float2(*(const __half2*)(g_B + (long long)gn * C + lane * 2));
            int i = 0;
            for (; i + 4 <= cnt; i += 4) {
                uint2 d0 = g_edat[start + i];
                uint2 d1 = g_edat[start + i + 1];
                uint2 d2 = g_edat[start + i + 2];
                uint2 d3 = g_edat[start + i + 3];
                float2 f0 = __half22float2(*(const __half2*)(g_A + (long long)d0.x * C + lane * 2));
                float2 f1 = __half22float2(*(const __half2*)(g_A + (long long)d1.x * C + lane * 2));
                float2 f2 = __half22float2(*(const __half2*)(g_A + (long long)d2.x * C + lane * 2));
                float2 f3 = __half22float2(*(const __half2*)(g_A + (long long)d3.x * C + lane * 2));
                float w0 = __uint_as_float(d0.y), w1 = __uint_as_float(d1.y);
                float w2 = __uint_as_float(d2.y), w3 = __uint_as_float(d3.y);
                acc.x += fmaxf(fmaf(w0, f0.x, bf.x), 0.f);
                acc.y += fmaxf(fmaf(w0, f0.y, bf.y), 0.f);
                acc.x += fmaxf(fmaf(w1, f1.x, bf.x), 0.f);
                acc.y += fmaxf(fmaf(w1, f1.y, bf.y), 0.f);
                acc.x += fmaxf(fmaf(w2, f2.x, bf.x), 0.f);
                acc.y += fmaxf(fmaf(w2, f2.y, bf.y), 0.f);
                acc.x += fmaxf(fmaf(w3, f3.x, bf.x), 0.f);
                acc.y += fmaxf(fmaf(w3, f3.y, bf.y), 0.f);
            }
            for (; i < cnt; i++) {
                uint2 d = g_edat[start + i];
                float2 f = __half22float2(*(const __half2*)(g_A + (long long)d.x * C + lane * 2));
                float w = __uint_as_float(d.y);
                acc.x += fmaxf(fmaf(w, f.x, bf.x), 0.f);
                acc.y += fmaxf(fmaf(w, f.y, bf.y), 0.f);
            }
        }
        hs[nl][lane * 2]     = round_tf32(acc.x);
        hs[nl][lane * 2 + 1] = round_tf32(acc.y);
    }

    // W2 tile
    for (int i = t; i < 64 * 16; i += 512) {
        int k  = i >> 4;
        int jc = (i & 15) * 4;
        float4 v = *(const float4*)(W2 + k * 64 + jc);
        ws2[k][jc + 0] = round_tf32(v.x);
        ws2[k][jc + 1] = round_tf32(v.y);
        ws2[k][jc + 2] = round_tf32(v.z);
        ws2[k][jc + 3] = round_tf32(v.w);
    }
    __syncthreads();

    // ---- Step B: MMA ----
    const int gid  = lane >> 2;
    const int t4   = lane & 3;
    const int m0   = (warp & 7) * 16;
    const int jb   = (warp >> 3) * 32;

    float acc[4][4];
    #pragma unroll
    for (int nt = 0; nt < 4; nt++)
        #pragma unroll
        for (int q = 0; q < 4; q++) acc[nt][q] = 0.f;

    #pragma unroll
    for (int slab = 0; slab < 8; slab++) {
        const int ks = slab * 8;
        unsigned a0 = __float_as_uint(hs[m0 + gid    ][ks + t4    ]);
        unsigned a1 = __float_as_uint(hs[m0 + gid + 8][ks + t4    ]);
        unsigned a2 = __float_as_uint(hs[m0 + gid    ][ks + t4 + 4]);
        unsigned a3 = __float_as_uint(hs[m0 + gid + 8][ks + t4 + 4]);
        #pragma unroll
        for (int nt = 0; nt < 4; nt++) {
            unsigned b0 = __float_as_uint(ws2[ks + t4    ][jb + nt * 8 + gid]);
            unsigned b1 = __float_as_uint(ws2[ks + t4 + 4][jb + nt * 8 + gid]);
            mma_tf32(acc[nt][0], acc[nt][1], acc[nt][2], acc[nt][3],
                     a0, a1, a2, a3, b0, b1);
        }
    }

    const int r0 = node0 + m0 + gid;
    const int r1 = r0 + 8;
    const float d0 = (r0 < N_NODES) ? (float)g_cnt[r0] : 0.f;
    const float d1 = (r1 < N_NODES) ? (float)g_cnt[r1] : 0.f;
    #pragma unroll
    for (int nt = 0; nt < 4; nt++) {
        int col = jb + nt * 8 + 2 * t4;
        float bx = b2[col], by = b2[col + 1];
        if (r0 < N_NODES) {
            float2 v = make_float2(acc[nt][0] + d0 * bx, acc[nt][1] + d0 * by);
            *(float2*)(out + (long long)r0 * C + col) = v;
        }
        if (r1 < N_NODES) {
            float2 v = make_float2(acc[nt][2] + d1 * bx, acc[nt][3] + d1 * by);
            *(float2*)(out + (long long)r1 * C + col) = v;
        }
    }
}

// ---------------------------------------------------------------------------
extern "C" void kernel_launch(void* const* d_in, const int* in_sizes, int n_in,
                              void* d_out, int out_size)
{
    const float* x  = (const float*)d_in[0];
    const void*  ei = (const void*)d_in[1];   // int32 or int64, detected on device
    const float* ea = (const float*)d_in[2];
    const float* W1 = (const float*)d_in[3];
    const float* b1 = (const float*)d_in[4];
    const float* W2 = (const float*)d_in[5];
    const float* b2 = (const float*)d_in[6];
    float* out = (float*)d_out;

    void* cntp;
    cudaGetSymbolAddress(&cntp, g_cnt);
    cudaMemsetAsync(cntp, 0, (size_t)N_NODES * sizeof(int));

    const int smem1  = (128 * XS_PAD + 64 * WS1_PAD) * 4;   // 69632
    const int smem23 = (128 * XS_PAD + 64 * WS2_PAD) * 4;   // 53248
    cudaFuncSetAttribute(phase1_kernel, cudaFuncAttributeMaxDynamicSharedMemorySize, smem1);
    cudaFuncSetAttribute(phase23_kernel, cudaFuncAttributeMaxDynamicSharedMemorySize, smem23);

    const int node_blocks = (N_NODES + 127) / 128;     // 782
    const int edge_blocks = (N_EDGES + 255) / 256;     // 3125
    const int scan_blocks = (N_NODES + 1023) / 1024;   // 98

    phase1_kernel<<<node_blocks, 512, smem1>>>(x, W1, b1, (const int*)ei);
    hist_kernel<<<edge_blocks, 256>>>(ei);
    scanA_kernel<<<scan_blocks, 1024>>>();
    scanC_kernel<<<scan_blocks, 1024>>>();
    scatter_kernel<<<edge_blocks, 256>>>(ei, ea);
    phase23_kernel<<<node_blocks, 512, smem23>>>(out, W2, b2);
}